// round 11
// baseline (speedup 1.0000x reference)
#include <cuda_runtime.h>
#include <cuda_fp16.h>
#include <math.h>
#include <stdint.h>

#define D 128
#define N_MAX 16384
#define BM 128
#define BNT 128
#define THREADS 640          // 4 SIMT warps (wid 0-3) + 16 HMMA warps (wid 4-19)
#define TW 512               // tensor-path threads
#define JCHUNKS 8
#define TTILES 14            // tensor tiles per chunk (SIMT takes 2)

// Scratch (allocation-free rule: __device__ globals)
__device__ __half g_z1h[N_MAX * D];   // fp16, pre-scaled by 2/ln2
__device__ __half g_z2h[N_MAX * D];   // fp16
__device__ float g_denom[N_MAX];
__device__ float g_pos[N_MAX];

// padded smem row stride: 128 fp16 + 8 pad = 136 elems = 272 bytes
#define SROW 272
#define TILE_BYTES (128 * SROW)          // 34816
#define OFF_A 0
#define OFF_B0 TILE_BYTES
#define OFF_B1 (2 * TILE_BYTES)
#define OFF_BS (3 * TILE_BYTES)          // SIMT static buffer: 2 tiles (256 rows)
#define OFF_RED (OFF_BS + 2 * TILE_BYTES)
#define SMEM_BYTES (OFF_RED + 128 * 4)   // 174592

__device__ __forceinline__ uint32_t smem_u32(const void* p) {
    uint32_t a;
    asm("{ .reg .u64 t; cvta.to.shared.u64 t, %1; cvt.u32.u64 %0, t; }"
        : "=r"(a) : "l"(p));
    return a;
}

__device__ __forceinline__ float warp_sum(float v) {
    #pragma unroll
    for (int off = 16; off > 0; off >>= 1)
        v += __shfl_xor_sync(0xFFFFFFFFu, v, off);
    return v;
}

// One warp per row: fp32 normalize, exact fp32 pos, fp16 copies; zero g_denom.
__global__ void norm_kernel(const float* __restrict__ z1,
                            const float* __restrict__ z2, int N) {
    int warp = (blockIdx.x * blockDim.x + threadIdx.x) >> 5;
    int lane = threadIdx.x & 31;
    if (warp >= N) return;

    const float4 a = ((const float4*)(z1 + (size_t)warp * D))[lane];
    const float4 b = ((const float4*)(z2 + (size_t)warp * D))[lane];

    float sa = a.x * a.x + a.y * a.y + a.z * a.z + a.w * a.w;
    float sb = b.x * b.x + b.y * b.y + b.z * b.z + b.w * b.w;
    sa = warp_sum(sa);
    sb = warp_sum(sb);

    float inva = 1.0f / fmaxf(sqrtf(sa), 1e-12f);
    float invb = 1.0f / fmaxf(sqrtf(sb), 1e-12f);

    float4 an = make_float4(a.x * inva, a.y * inva, a.z * inva, a.w * inva);
    float4 bn = make_float4(b.x * invb, b.y * invb, b.z * invb, b.w * invb);

    // bake exponent scale 2/ln2 into A so epilogue is a bare ex2.approx
    const float S = 2.8853900817779268f;
    __half2 a01 = __floats2half2_rn(an.x * S, an.y * S);
    __half2 a23 = __floats2half2_rn(an.z * S, an.w * S);
    __half2 b01 = __floats2half2_rn(bn.x, bn.y);
    __half2 b23 = __floats2half2_rn(bn.z, bn.w);

    uint2 pa, pb;
    pa.x = *(uint32_t*)&a01; pa.y = *(uint32_t*)&a23;
    pb.x = *(uint32_t*)&b01; pb.y = *(uint32_t*)&b23;
    ((uint2*)(g_z1h + (size_t)warp * D))[lane] = pa;
    ((uint2*)(g_z2h + (size_t)warp * D))[lane] = pb;

    float d = an.x * bn.x + an.y * bn.y + an.z * bn.z + an.w * bn.w;
    d = warp_sum(d);
    if (lane == 0) {
        g_pos[warp] = 2.0f * d;
        g_denom[warp] = 0.0f;
    }
}

__device__ __forceinline__ void ldsm_x4(uint32_t (&r)[4], uint32_t addr) {
    asm volatile("ldmatrix.sync.aligned.m8n8.x4.shared.b16 {%0,%1,%2,%3}, [%4];"
                 : "=r"(r[0]), "=r"(r[1]), "=r"(r[2]), "=r"(r[3]) : "r"(addr));
}

// fp16 in, fp16 accum: C/D fragments are 2 regs of f16x2
__device__ __forceinline__ void hmma_f16acc(uint32_t (&c)[2], const uint32_t (&a)[4],
                                            uint32_t b0, uint32_t b1) {
    asm volatile(
        "mma.sync.aligned.m16n8k16.row.col.f16.f16.f16.f16 "
        "{%0,%1}, {%2,%3,%4,%5}, {%6,%7}, {%0,%1};"
        : "+r"(c[0]), "+r"(c[1])
        : "r"(a[0]), "r"(a[1]), "r"(a[2]), "r"(a[3]), "r"(b0), "r"(b1));
}

__device__ __forceinline__ void cp16(uint32_t dst, const void* src) {
    asm volatile("cp.async.cg.shared.global [%0], [%1], 16;"
                 :: "r"(dst), "l"(src) : "memory");
}

// One tile's k-loop accumulating into `acc`, with the epilogue of the
// PREVIOUS tile (`cprev`) interleaved one fragment-group per kk step.
__device__ __forceinline__ void tile_step(
    uint32_t (&acc)[2][4][2], uint32_t (&cprev)[2][4][2],
    uint32_t a_base, uint32_t b_base, float (&rs)[4]) {
    #pragma unroll
    for (int kk = 0; kk < 8; ++kk) {
        const uint32_t koff = (uint32_t)kk * 32;
        uint32_t a[2][4];
        #pragma unroll
        for (int mf = 0; mf < 2; ++mf)
            ldsm_x4(a[mf], a_base + (uint32_t)(mf * 16) * SROW + koff);
        uint32_t bm[2][4];
        #pragma unroll
        for (int nf2 = 0; nf2 < 2; ++nf2)
            ldsm_x4(bm[nf2], b_base + (uint32_t)(nf2 * 16) * SROW + koff);

        #pragma unroll
        for (int mf = 0; mf < 2; ++mf)
            #pragma unroll
            for (int nf = 0; nf < 4; ++nf)
                hmma_f16acc(acc[mf][nf], a[mf],
                            bm[nf >> 1][nf & 1], bm[nf >> 1][(nf & 1) + 2]);

        {   // deferred epilogue chunk: fragment group = kk of previous tile
            const int mf = kk >> 2, nf = kk & 3;
            float2 f0 = __half22float2(*(__half2*)&cprev[mf][nf][0]);
            float2 f1 = __half22float2(*(__half2*)&cprev[mf][nf][1]);
            float e0, e1, e2, e3;
            asm("ex2.approx.f32 %0, %1;" : "=f"(e0) : "f"(f0.x));
            asm("ex2.approx.f32 %0, %1;" : "=f"(e1) : "f"(f0.y));
            asm("ex2.approx.f32 %0, %1;" : "=f"(e2) : "f"(f1.x));
            asm("ex2.approx.f32 %0, %1;" : "=f"(e3) : "f"(f1.y));
            rs[mf * 2 + 0] += e0 + e1;
            rs[mf * 2 + 1] += e2 + e3;
            cprev[mf][nf][0] = 0u;
            cprev[mf][nf][1] = 0u;
        }
    }
}

// ---------------------------------------------------------------------------
// Hybrid tensor+SIMT GEMM + fused exp/rowsum.
// Warps 4-19 (HIGH wid = issue priority): HMMA on 14 tiles, barrier 1 (512).
// Warps 0-3 (LOW wid = fill idle issue slots): HFMA2 SIMT on 2 tiles.
// Tile 0's bogus epilogue (zeros) adds 128*JCHUNKS per row; fixed in loss.
// ---------------------------------------------------------------------------
__global__ void __launch_bounds__(THREADS, 1)
gemm_hybrid_kernel(int N) {
    extern __shared__ char smem[];
    const uint32_t sb = smem_u32(smem);
    const int tid = threadIdx.x;
    const int wid = tid >> 5;
    const int lane = tid & 31;
    const int i0 = blockIdx.x * BM;
    const int jt0 = blockIdx.y * (TTILES + 2);   // 16 tiles of column space per chunk
    float* red = (float*)(smem + OFF_RED);

    // ---- converged prologue (all 640 threads) ----
    {   // A tile 128x128 fp16 (plain stores)
        const uint4* A4 = (const uint4*)(g_z1h + (size_t)i0 * D);
        for (int idx = tid; idx < 2048; idx += THREADS) {
            int r = idx >> 4, c = idx & 15;
            *(uint4*)(smem + OFF_A + r * SROW + c * 16) = A4[idx];
        }
    }
    {   // SIMT static buffer: tiles jt0+14, jt0+15 (256 contiguous z2 rows)
        const char* B = (const char*)(g_z2h + (size_t)(jt0 + TTILES) * BNT * D);
        for (int idx = tid; idx < 4096; idx += THREADS) {
            int r = idx >> 4, c = idx & 15;
            cp16(sb + OFF_BS + r * SROW + c * 16, B + (size_t)r * 256 + c * 16);
        }
        asm volatile("cp.async.commit_group;" ::: "memory");
    }
    {   // B tile jt0 -> buf0
        const char* B = (const char*)(g_z2h + (size_t)jt0 * BNT * D);
        for (int idx = tid; idx < 2048; idx += THREADS) {
            int r = idx >> 4, c = idx & 15;
            cp16(sb + OFF_B0 + r * SROW + c * 16, B + (size_t)r * 256 + c * 16);
        }
        asm volatile("cp.async.commit_group;" ::: "memory");
    }
    asm volatile("cp.async.wait_group 0;" ::: "memory");
    if (tid < 128) red[tid] = 0.f;
    __syncthreads();   // converged: A, BS, buf0, red all ready

    if (wid >= 4) {
        // ========== tensor path (wid 4-19, issue priority) ==========
        const int ttid = tid - 128;       // 0..511
        const int twid = wid - 4;         // 0..15
        const int warp_m = twid >> 2;
        const int warp_n = twid & 3;
        const uint32_t a_base = sb + OFF_A +
            (uint32_t)(warp_m * 32 + (lane & 15)) * SROW + (uint32_t)((lane >> 4) * 16);
        const uint32_t b_lane_off =
            (uint32_t)(warp_n * 32 + (lane & 15)) * SROW + (uint32_t)((lane >> 4) * 16);
        const uint32_t b_base0 = sb + OFF_B0 + b_lane_off;
        const uint32_t b_base1 = sb + OFF_B1 + b_lane_off;

        uint32_t c0[2][4][2], c1[2][4][2];
        #pragma unroll
        for (int mf = 0; mf < 2; ++mf)
            #pragma unroll
            for (int nf = 0; nf < 4; ++nf) {
                c0[mf][nf][0] = 0u; c0[mf][nf][1] = 0u;
                c1[mf][nf][0] = 0u; c1[mf][nf][1] = 0u;
            }
        float rs[4] = {0.f, 0.f, 0.f, 0.f};

        for (int t = 0; t < TTILES; t += 2) {
            // sub-iter A: tile t (buf0, acc c0, deferred epilogue c1)
            asm volatile("bar.sync 1, 512;" ::: "memory");   // done reading buf1
            {   // prefetch tile t+1 -> buf1 (t+1 < TTILES; TTILES even)
                const char* B = (const char*)(g_z2h + (size_t)(jt0 + t + 1) * BNT * D);
                #pragma unroll
                for (int u = 0; u < 4; ++u) {
                    int idx = ttid + u * TW;
                    int r = idx >> 4, ch = idx & 15;
                    cp16(sb + OFF_B1 + r * SROW + ch * 16, B + (size_t)r * 256 + ch * 16);
                }
                asm volatile("cp.async.commit_group;" ::: "memory");
                asm volatile("cp.async.wait_group 1;" ::: "memory");
            }
            asm volatile("bar.sync 1, 512;" ::: "memory");   // buf0 visible
            tile_step(c0, c1, a_base, b_base0, rs);

            // sub-iter B: tile t+1 (buf1, acc c1, deferred epilogue c0)
            asm volatile("bar.sync 1, 512;" ::: "memory");   // done reading buf0
            if (t + 2 < TTILES) {
                const char* B = (const char*)(g_z2h + (size_t)(jt0 + t + 2) * BNT * D);
                #pragma unroll
                for (int u = 0; u < 4; ++u) {
                    int idx = ttid + u * TW;
                    int r = idx >> 4, ch = idx & 15;
                    cp16(sb + OFF_B0 + r * SROW + ch * 16, B + (size_t)r * 256 + ch * 16);
                }
                asm volatile("cp.async.commit_group;" ::: "memory");
                asm volatile("cp.async.wait_group 1;" ::: "memory");
            } else {
                asm volatile("cp.async.wait_group 0;" ::: "memory");
            }
            asm volatile("bar.sync 1, 512;" ::: "memory");   // buf1 visible
            tile_step(c1, c0, a_base, b_base1, rs);
        }

        // final epilogue: c1 holds tile TTILES-1
        #pragma unroll
        for (int mf = 0; mf < 2; ++mf) {
            float lo = 0.f, hi = 0.f;
            #pragma unroll
            for (int nf = 0; nf < 4; ++nf) {
                float2 f0 = __half22float2(*(__half2*)&c1[mf][nf][0]);
                float2 f1 = __half22float2(*(__half2*)&c1[mf][nf][1]);
                float e0, e1, e2, e3;
                asm("ex2.approx.f32 %0, %1;" : "=f"(e0) : "f"(f0.x));
                asm("ex2.approx.f32 %0, %1;" : "=f"(e1) : "f"(f0.y));
                asm("ex2.approx.f32 %0, %1;" : "=f"(e2) : "f"(f1.x));
                asm("ex2.approx.f32 %0, %1;" : "=f"(e3) : "f"(f1.y));
                lo += e0 + e1;
                hi += e2 + e3;
            }
            rs[mf * 2 + 0] += lo;
            rs[mf * 2 + 1] += hi;
        }
        #pragma unroll
        for (int i = 0; i < 4; ++i) {
            rs[i] += __shfl_xor_sync(0xFFFFFFFFu, rs[i], 1);
            rs[i] += __shfl_xor_sync(0xFFFFFFFFu, rs[i], 2);
        }
        if ((lane & 3) == 0) {
            #pragma unroll
            for (int mf = 0; mf < 2; ++mf)
                #pragma unroll
                for (int sub = 0; sub < 2; ++sub) {
                    int row = warp_m * 32 + mf * 16 + sub * 8 + (lane >> 2);
                    atomicAdd(&red[row], rs[mf * 2 + sub]);
                }
        }
    } else {
        // ========== SIMT path (wid 0-3, lowest priority: fills idle slots) ==
        const int swid = wid;             // 0..3 -> rows swid*32..+31
        const int tr = lane >> 3;         // 0..3
        const int tc = lane & 7;          // 0..7
        // rows: swid*32 + 4i + tr (i<8); cols per pass: pass*16 + tc + 8j (j<2)
        const char* As = smem + OFF_A + (uint32_t)(swid * 32 + tr) * SROW;

        float rsim[8];
        #pragma unroll
        for (int i = 0; i < 8; ++i) rsim[i] = 0.f;

        for (int pass = 0; pass < 16; ++pass) {
            const char* Bp = smem + OFF_BS + (uint32_t)(pass * 16 + tc) * SROW;
            __half2 acc[8][2];
            #pragma unroll
            for (int i = 0; i < 8; ++i) {
                acc[i][0] = __floats2half2_rn(0.f, 0.f);
                acc[i][1] = __floats2half2_rn(0.f, 0.f);
            }

            #pragma unroll 2
            for (int q = 0; q < 16; ++q) {      // q covers k2 in [4q, 4q+4)
                float4 av4[8], bv4[2];
                #pragma unroll
                for (int i = 0; i < 8; ++i)
                    av4[i] = *(const float4*)(As + (uint32_t)(4 * i) * SROW + q * 16);
                #pragma unroll
                for (int j = 0; j < 2; ++j)
                    bv4[j] = *(const float4*)(Bp + (uint32_t)(8 * j) * SROW + q * 16);

                #pragma unroll
                for (int s = 0; s < 4; ++s) {
                    #pragma unroll
                    for (int i = 0; i < 8; ++i) {
                        __half2 a2 = ((const __half2*)&av4[i])[s];
                        #pragma unroll
                        for (int j = 0; j < 2; ++j) {
                            __half2 b2 = ((const __half2*)&bv4[j])[s];
                            acc[i][j] = __hfma2(a2, b2, acc[i][j]);
                        }
                    }
                }
            }

            #pragma unroll
            for (int i = 0; i < 8; ++i) {
                float s = 0.f;
                #pragma unroll
                for (int j = 0; j < 2; ++j) {
                    float2 f = __half22float2(acc[i][j]);
                    float e;
                    asm("ex2.approx.f32 %0, %1;" : "=f"(e) : "f"(f.x + f.y));
                    s += e;
                }
                rsim[i] += s;
            }
        }

        // reduce over tc (8 lanes within each tr group), then atomicAdd
        #pragma unroll
        for (int i = 0; i < 8; ++i) {
            rsim[i] += __shfl_xor_sync(0xFFFFFFFFu, rsim[i], 1);
            rsim[i] += __shfl_xor_sync(0xFFFFFFFFu, rsim[i], 2);
            rsim[i] += __shfl_xor_sync(0xFFFFFFFFu, rsim[i], 4);
        }
        if (tc == 0) {
            #pragma unroll
            for (int i = 0; i < 8; ++i)
                atomicAdd(&red[swid * 32 + 4 * i + tr], rsim[i]);
        }
    }

    __syncthreads();   // converged
    if (tid < 128) atomicAdd(&g_denom[i0 + tid], red[tid]);
}

__global__ void loss_kernel(float* __restrict__ out, int N) {
    __shared__ float smr[256];
    float s = 0.f;
    // subtract bogus first-epilogue: JCHUNKS * 128 * ex2(0) per row
    const float BOGUS = 128.0f * (float)JCHUNKS;
    for (int i = threadIdx.x; i < N; i += 256)
        s += logf(g_denom[i] - BOGUS + 1e-8f) - g_pos[i];
    smr[threadIdx.x] = s;
    __syncthreads();
    #pragma unroll
    for (int off = 128; off > 0; off >>= 1) {
        if (threadIdx.x < off) smr[threadIdx.x] += smr[threadIdx.x + off];
        __syncthreads();
    }
    if (threadIdx.x == 0) out[0] = smr[0] / (float)N;
}

extern "C" void kernel_launch(void* const* d_in, const int* in_sizes, int n_in,
                              void* d_out, int out_size) {
    const float* z1 = (const float*)d_in[0];
    const float* z2 = (const float*)d_in[1];
    float* out = (float*)d_out;
    const int N = in_sizes[0] / D;  // 16384

    cudaFuncSetAttribute(gemm_hybrid_kernel,
                         cudaFuncAttributeMaxDynamicSharedMemorySize,
                         (int)SMEM_BYTES);

    norm_kernel<<<(N + 7) / 8, 256>>>(z1, z2, N);
    dim3 grid(N / BM, JCHUNKS);
    gemm_hybrid_kernel<<<grid, THREADS, SMEM_BYTES>>>(N);
    loss_kernel<<<1, 256>>>(out, N);
}

// round 12
// speedup vs baseline: 1.4359x; 1.4359x over previous
#include <cuda_runtime.h>
#include <cuda_fp16.h>
#include <math.h>
#include <stdint.h>

#define D 128
#define N_MAX 16384
#define BM 128
#define BNT 128
#define THREADS 512
#define JCHUNKS 8

// Scratch (allocation-free rule: __device__ globals)
__device__ __half g_z1h[N_MAX * D];   // fp16, pre-scaled by 2/ln2
__device__ __half g_z2h[N_MAX * D];   // fp16
__device__ float g_denom[N_MAX];
__device__ float g_pos[N_MAX];

// padded smem row stride: 128 fp16 + 8 pad = 136 elems = 272 bytes
#define SROW 272
#define TILE_BYTES (128 * SROW)          // 34816
#define OFF_A 0
#define OFF_B0 TILE_BYTES
#define OFF_B1 (2 * TILE_BYTES)
#define OFF_RED (3 * TILE_BYTES)
#define SMEM_BYTES (OFF_RED + 128 * 4)

__device__ __forceinline__ uint32_t smem_u32(const void* p) {
    uint32_t a;
    asm("{ .reg .u64 t; cvta.to.shared.u64 t, %1; cvt.u32.u64 %0, t; }"
        : "=r"(a) : "l"(p));
    return a;
}

__device__ __forceinline__ float warp_sum(float v) {
    #pragma unroll
    for (int off = 16; off > 0; off >>= 1)
        v += __shfl_xor_sync(0xFFFFFFFFu, v, off);
    return v;
}

// Zero g_denom (also shifts ncu -s alignment so gemm can get profiled).
__global__ void zero_kernel(int N) {
    int i = blockIdx.x * blockDim.x + threadIdx.x;
    if (i < N) g_denom[i] = 0.0f;
}

// 4 rows per warp, all loads issued up-front (MLP 8):
// fp32 normalize, exact fp32 pos, fp16 copies (z1 pre-scaled by 2/ln2).
__global__ void norm_kernel(const float* __restrict__ z1,
                            const float* __restrict__ z2, int N) {
    int warp = (blockIdx.x * blockDim.x + threadIdx.x) >> 5;
    int lane = threadIdx.x & 31;
    int r0 = warp * 4;
    if (r0 >= N) return;

    float4 a[4], b[4];
    #pragma unroll
    for (int i = 0; i < 4; ++i) {
        a[i] = ((const float4*)(z1 + (size_t)(r0 + i) * D))[lane];
        b[i] = ((const float4*)(z2 + (size_t)(r0 + i) * D))[lane];
    }

    const float S = 2.8853900817779268f;   // 2/ln2 baked into A
    #pragma unroll
    for (int i = 0; i < 4; ++i) {
        float sa = a[i].x * a[i].x + a[i].y * a[i].y +
                   a[i].z * a[i].z + a[i].w * a[i].w;
        float sb = b[i].x * b[i].x + b[i].y * b[i].y +
                   b[i].z * b[i].z + b[i].w * b[i].w;
        sa = warp_sum(sa);
        sb = warp_sum(sb);

        float inva = 1.0f / fmaxf(sqrtf(sa), 1e-12f);
        float invb = 1.0f / fmaxf(sqrtf(sb), 1e-12f);

        float4 an = make_float4(a[i].x * inva, a[i].y * inva,
                                a[i].z * inva, a[i].w * inva);
        float4 bn = make_float4(b[i].x * invb, b[i].y * invb,
                                b[i].z * invb, b[i].w * invb);

        __half2 a01 = __floats2half2_rn(an.x * S, an.y * S);
        __half2 a23 = __floats2half2_rn(an.z * S, an.w * S);
        __half2 b01 = __floats2half2_rn(bn.x, bn.y);
        __half2 b23 = __floats2half2_rn(bn.z, bn.w);

        uint2 pa, pb;
        pa.x = *(uint32_t*)&a01; pa.y = *(uint32_t*)&a23;
        pb.x = *(uint32_t*)&b01; pb.y = *(uint32_t*)&b23;
        ((uint2*)(g_z1h + (size_t)(r0 + i) * D))[lane] = pa;
        ((uint2*)(g_z2h + (size_t)(r0 + i) * D))[lane] = pb;

        float d = an.x * bn.x + an.y * bn.y + an.z * bn.z + an.w * bn.w;
        d = warp_sum(d);
        if (lane == 0) g_pos[r0 + i] = 2.0f * d;
    }
}

__device__ __forceinline__ void ldsm_x4(uint32_t (&r)[4], uint32_t addr) {
    asm volatile("ldmatrix.sync.aligned.m8n8.x4.shared.b16 {%0,%1,%2,%3}, [%4];"
                 : "=r"(r[0]), "=r"(r[1]), "=r"(r[2]), "=r"(r[3]) : "r"(addr));
}

// fp16 in, fp16 accum: C/D fragments are 2 regs of f16x2
__device__ __forceinline__ void hmma_f16acc(uint32_t (&c)[2], const uint32_t (&a)[4],
                                            uint32_t b0, uint32_t b1) {
    asm volatile(
        "mma.sync.aligned.m16n8k16.row.col.f16.f16.f16.f16 "
        "{%0,%1}, {%2,%3,%4,%5}, {%6,%7}, {%0,%1};"
        : "+r"(c[0]), "+r"(c[1])
        : "r"(a[0]), "r"(a[1]), "r"(a[2]), "r"(a[3]), "r"(b0), "r"(b1));
}

__device__ __forceinline__ void cp16(uint32_t dst, const void* src) {
    asm volatile("cp.async.cg.shared.global [%0], [%1], 16;"
                 :: "r"(dst), "l"(src) : "memory");
}

// One tile's k-loop accumulating into `acc`, with the epilogue of the
// PREVIOUS tile (`cprev`) interleaved one fragment-group per kk step.
// All register-array indices are compile-time (no spills).
__device__ __forceinline__ void tile_step(
    uint32_t (&acc)[2][4][2], uint32_t (&cprev)[2][4][2],
    uint32_t a_base, uint32_t b_base, float (&rs)[4]) {
    #pragma unroll
    for (int kk = 0; kk < 8; ++kk) {
        const uint32_t koff = (uint32_t)kk * 32;
        uint32_t a[2][4];
        #pragma unroll
        for (int mf = 0; mf < 2; ++mf)
            ldsm_x4(a[mf], a_base + (uint32_t)(mf * 16) * SROW + koff);
        uint32_t bm[2][4];
        #pragma unroll
        for (int nf2 = 0; nf2 < 2; ++nf2)
            ldsm_x4(bm[nf2], b_base + (uint32_t)(nf2 * 16) * SROW + koff);

        #pragma unroll
        for (int mf = 0; mf < 2; ++mf)
            #pragma unroll
            for (int nf = 0; nf < 4; ++nf)
                hmma_f16acc(acc[mf][nf], a[mf],
                            bm[nf >> 1][nf & 1], bm[nf >> 1][(nf & 1) + 2]);

        {   // deferred epilogue chunk: fragment group = kk of previous tile
            const int mf = kk >> 2, nf = kk & 3;
            float2 f0 = __half22float2(*(__half2*)&cprev[mf][nf][0]);
            float2 f1 = __half22float2(*(__half2*)&cprev[mf][nf][1]);
            float e0, e1, e2, e3;
            asm("ex2.approx.f32 %0, %1;" : "=f"(e0) : "f"(f0.x));
            asm("ex2.approx.f32 %0, %1;" : "=f"(e1) : "f"(f0.y));
            asm("ex2.approx.f32 %0, %1;" : "=f"(e2) : "f"(f1.x));
            asm("ex2.approx.f32 %0, %1;" : "=f"(e3) : "f"(f1.y));
            rs[mf * 2 + 0] += e0 + e1;
            rs[mf * 2 + 1] += e2 + e3;
            cprev[mf][nf][0] = 0u;
            cprev[mf][nf][1] = 0u;
        }
    }
}

// ---------------------------------------------------------------------------
// FP16-accum HMMA GEMM + fused deferred exp/rowsum (R9 structure, verified).
// Grid (N/128 row-tiles, JCHUNKS j-chunks), 512 threads (16 warps 4x4).
// Warp tile 32x32. A persistent; B double-buffered; loop unrolled x2 with
// static accumulator sets c0/c1. Tile 0's bogus epilogue of zeros adds
// exactly 128*JCHUNKS per row; subtracted in loss_kernel.
// ---------------------------------------------------------------------------
__global__ void __launch_bounds__(THREADS, 1)
gemm_hmma16_kernel(int N) {
    extern __shared__ char smem[];
    const uint32_t sb = smem_u32(smem);
    const int tid = threadIdx.x;
    const int wid = tid >> 5;
    const int lane = tid & 31;
    const int warp_m = wid >> 2;      // 0..3
    const int warp_n = wid & 3;       // 0..3
    const int i0 = blockIdx.x * BM;
    const int T = (N / BNT) / JCHUNKS;   // 16 tiles per chunk (even)
    const int jt0 = blockIdx.y * T;

    // Load A tile (128x128 fp16) into padded smem.
    {
        const uint4* A4 = (const uint4*)(g_z1h + (size_t)i0 * D);
        #pragma unroll
        for (int t = 0; t < 4; ++t) {
            int idx = tid + t * THREADS;        // 0..2047
            int r = idx >> 4, c = idx & 15;
            *(uint4*)(smem + OFF_A + r * SROW + c * 16) = A4[idx];
        }
    }

    // Prologue: B tile jt0 -> buf0
    {
        const char* B = (const char*)(g_z2h + (size_t)jt0 * BNT * D);
        #pragma unroll
        for (int t = 0; t < 4; ++t) {
            int idx = tid + t * THREADS;
            int r = idx >> 4, c = idx & 15;
            cp16(sb + OFF_B0 + r * SROW + c * 16, B + (size_t)r * 256 + c * 16);
        }
        asm volatile("cp.async.commit_group;" ::: "memory");
    }

    const uint32_t a_base = sb + OFF_A +
        (uint32_t)(warp_m * 32 + (lane & 15)) * SROW + (uint32_t)((lane >> 4) * 16);
    const uint32_t b_lane_off =
        (uint32_t)(warp_n * 32 + (lane & 15)) * SROW + (uint32_t)((lane >> 4) * 16);
    const uint32_t b_base0 = sb + OFF_B0 + b_lane_off;
    const uint32_t b_base1 = sb + OFF_B1 + b_lane_off;

    uint32_t c0[2][4][2], c1[2][4][2];
    #pragma unroll
    for (int mf = 0; mf < 2; ++mf)
        #pragma unroll
        for (int nf = 0; nf < 4; ++nf) {
            c0[mf][nf][0] = 0u; c0[mf][nf][1] = 0u;
            c1[mf][nf][0] = 0u; c1[mf][nf][1] = 0u;
        }

    float rs[4] = {0.f, 0.f, 0.f, 0.f};

    for (int t = 0; t < T; t += 2) {
        // ---- sub-iter A: tile t (buf0, acc c0, epilogue c1 = tile t-1) ----
        __syncthreads();   // everyone done reading buf1
        {   // t+1 < T always (T even, t <= T-2)
            const char* B = (const char*)(g_z2h + (size_t)(jt0 + t + 1) * BNT * D);
            #pragma unroll
            for (int u = 0; u < 4; ++u) {
                int idx = tid + u * THREADS;
                int r = idx >> 4, ch = idx & 15;
                cp16(sb + OFF_B1 + r * SROW + ch * 16, B + (size_t)r * 256 + ch * 16);
            }
            asm volatile("cp.async.commit_group;" ::: "memory");
            asm volatile("cp.async.wait_group 1;" ::: "memory");
        }
        __syncthreads();   // buf0 visible
        tile_step(c0, c1, a_base, b_base0, rs);

        // ---- sub-iter B: tile t+1 (buf1, acc c1, epilogue c0 = tile t) ----
        __syncthreads();   // everyone done reading buf0
        if (t + 2 < T) {
            const char* B = (const char*)(g_z2h + (size_t)(jt0 + t + 2) * BNT * D);
            #pragma unroll
            for (int u = 0; u < 4; ++u) {
                int idx = tid + u * THREADS;
                int r = idx >> 4, ch = idx & 15;
                cp16(sb + OFF_B0 + r * SROW + ch * 16, B + (size_t)r * 256 + ch * 16);
            }
            asm volatile("cp.async.commit_group;" ::: "memory");
            asm volatile("cp.async.wait_group 1;" ::: "memory");
        } else {
            asm volatile("cp.async.wait_group 0;" ::: "memory");
        }
        __syncthreads();   // buf1 visible
        tile_step(c1, c0, a_base, b_base1, rs);
    }

    // final epilogue: c1 holds tile T-1
    #pragma unroll
    for (int mf = 0; mf < 2; ++mf) {
        float lo = 0.f, hi = 0.f;
        #pragma unroll
        for (int nf = 0; nf < 4; ++nf) {
            float2 f0 = __half22float2(*(__half2*)&c1[mf][nf][0]);
            float2 f1 = __half22float2(*(__half2*)&c1[mf][nf][1]);
            float e0, e1, e2, e3;
            asm("ex2.approx.f32 %0, %1;" : "=f"(e0) : "f"(f0.x));
            asm("ex2.approx.f32 %0, %1;" : "=f"(e1) : "f"(f0.y));
            asm("ex2.approx.f32 %0, %1;" : "=f"(e2) : "f"(f1.x));
            asm("ex2.approx.f32 %0, %1;" : "=f"(e3) : "f"(f1.y));
            lo += e0 + e1;
            hi += e2 + e3;
        }
        rs[mf * 2 + 0] += lo;
        rs[mf * 2 + 1] += hi;
    }

    // reduce rs across the 4 lanes of each quad (same row group)
    #pragma unroll
    for (int i = 0; i < 4; ++i) {
        rs[i] += __shfl_xor_sync(0xFFFFFFFFu, rs[i], 1);
        rs[i] += __shfl_xor_sync(0xFFFFFFFFu, rs[i], 2);
    }

    float* red = (float*)(smem + OFF_RED);
    __syncthreads();
    if (tid < 128) red[tid] = 0.f;
    __syncthreads();
    if ((lane & 3) == 0) {
        #pragma unroll
        for (int mf = 0; mf < 2; ++mf) {
            #pragma unroll
            for (int sub = 0; sub < 2; ++sub) {
                int row = warp_m * 32 + mf * 16 + sub * 8 + (lane >> 2);
                atomicAdd(&red[row], rs[mf * 2 + sub]);
            }
        }
    }
    __syncthreads();
    if (tid < 128) atomicAdd(&g_denom[i0 + tid], red[tid]);
}

__global__ void loss_kernel(float* __restrict__ out, int N) {
    __shared__ float smr[1024];
    float s = 0.f;
    // subtract bogus first-epilogue: JCHUNKS * 128 * ex2(0) per row
    const float BOGUS = 128.0f * (float)JCHUNKS;
    const float4* d4 = (const float4*)g_denom;
    const float4* p4 = (const float4*)g_pos;
    for (int i = threadIdx.x; i < N / 4; i += 1024) {
        float4 dv = d4[i];
        float4 pv = p4[i];
        s += logf(dv.x - BOGUS + 1e-8f) - pv.x;
        s += logf(dv.y - BOGUS + 1e-8f) - pv.y;
        s += logf(dv.z - BOGUS + 1e-8f) - pv.z;
        s += logf(dv.w - BOGUS + 1e-8f) - pv.w;
    }
    smr[threadIdx.x] = s;
    __syncthreads();
    #pragma unroll
    for (int off = 512; off > 0; off >>= 1) {
        if (threadIdx.x < off) smr[threadIdx.x] += smr[threadIdx.x + off];
        __syncthreads();
    }
    if (threadIdx.x == 0) out[0] = smr[0] / (float)N;
}

extern "C" void kernel_launch(void* const* d_in, const int* in_sizes, int n_in,
                              void* d_out, int out_size) {
    const float* z1 = (const float*)d_in[0];
    const float* z2 = (const float*)d_in[1];
    float* out = (float*)d_out;
    const int N = in_sizes[0] / D;  // 16384

    cudaFuncSetAttribute(gemm_hmma16_kernel,
                         cudaFuncAttributeMaxDynamicSharedMemorySize,
                         (int)SMEM_BYTES);

    zero_kernel<<<N / 256, 256>>>(N);
    norm_kernel<<<N / 32, 256>>>(z1, z2, N);   // 4 rows/warp, 8 warps/block
    dim3 grid(N / BM, JCHUNKS);
    gemm_hmma16_kernel<<<grid, THREADS, SMEM_BYTES>>>(N);
    loss_kernel<<<1, 1024>>>(out, N);
}

// round 13
// speedup vs baseline: 1.4490x; 1.0091x over previous
#include <cuda_runtime.h>
#include <cuda_fp16.h>
#include <math.h>
#include <stdint.h>

#define D 128
#define N_MAX 16384
#define BM 128
#define BNT 128
#define THREADS 512
#define JCHUNKS 8

// Scratch (allocation-free rule: __device__ globals)
__device__ __half g_z1h[N_MAX * D];   // fp16, pre-scaled by 2/ln2
__device__ __half g_z2h[N_MAX * D];   // fp16
__device__ float g_denom[N_MAX];
__device__ float g_pos[N_MAX];

// padded smem row stride: 128 fp16 + 8 pad = 136 elems = 272 bytes
#define SROW 272
#define TILE_BYTES (128 * SROW)          // 34816
#define OFF_A 0
#define OFF_B0 TILE_BYTES
#define OFF_B1 (2 * TILE_BYTES)
#define OFF_RED (3 * TILE_BYTES)
#define SMEM_BYTES (OFF_RED + 128 * 4)

__device__ __forceinline__ uint32_t smem_u32(const void* p) {
    uint32_t a;
    asm("{ .reg .u64 t; cvta.to.shared.u64 t, %1; cvt.u32.u64 %0, t; }"
        : "=r"(a) : "l"(p));
    return a;
}

__device__ __forceinline__ float warp_sum(float v) {
    #pragma unroll
    for (int off = 16; off > 0; off >>= 1)
        v += __shfl_xor_sync(0xFFFFFFFFu, v, off);
    return v;
}

// 4 rows per warp, all loads issued up-front (MLP 8):
// fp32 normalize, exact fp32 pos, fp16 copies (z1 pre-scaled by 2/ln2).
// Also zeroes g_denom rows and out[0] (consumed by the atomic loss reduce).
__global__ void norm_kernel(const float* __restrict__ z1,
                            const float* __restrict__ z2,
                            float* __restrict__ out, int N) {
    int warp = (blockIdx.x * blockDim.x + threadIdx.x) >> 5;
    int lane = threadIdx.x & 31;
    int r0 = warp * 4;
    if (blockIdx.x == 0 && threadIdx.x == 0) out[0] = 0.0f;
    if (r0 >= N) return;

    float4 a[4], b[4];
    #pragma unroll
    for (int i = 0; i < 4; ++i) {
        a[i] = ((const float4*)(z1 + (size_t)(r0 + i) * D))[lane];
        b[i] = ((const float4*)(z2 + (size_t)(r0 + i) * D))[lane];
    }

    const float S = 2.8853900817779268f;   // 2/ln2 baked into A
    #pragma unroll
    for (int i = 0; i < 4; ++i) {
        float sa = a[i].x * a[i].x + a[i].y * a[i].y +
                   a[i].z * a[i].z + a[i].w * a[i].w;
        float sb = b[i].x * b[i].x + b[i].y * b[i].y +
                   b[i].z * b[i].z + b[i].w * b[i].w;
        sa = warp_sum(sa);
        sb = warp_sum(sb);

        float inva = 1.0f / fmaxf(sqrtf(sa), 1e-12f);
        float invb = 1.0f / fmaxf(sqrtf(sb), 1e-12f);

        float4 an = make_float4(a[i].x * inva, a[i].y * inva,
                                a[i].z * inva, a[i].w * inva);
        float4 bn = make_float4(b[i].x * invb, b[i].y * invb,
                                b[i].z * invb, b[i].w * invb);

        __half2 a01 = __floats2half2_rn(an.x * S, an.y * S);
        __half2 a23 = __floats2half2_rn(an.z * S, an.w * S);
        __half2 b01 = __floats2half2_rn(bn.x, bn.y);
        __half2 b23 = __floats2half2_rn(bn.z, bn.w);

        uint2 pa, pb;
        pa.x = *(uint32_t*)&a01; pa.y = *(uint32_t*)&a23;
        pb.x = *(uint32_t*)&b01; pb.y = *(uint32_t*)&b23;
        ((uint2*)(g_z1h + (size_t)(r0 + i) * D))[lane] = pa;
        ((uint2*)(g_z2h + (size_t)(r0 + i) * D))[lane] = pb;

        float d = an.x * bn.x + an.y * bn.y + an.z * bn.z + an.w * bn.w;
        d = warp_sum(d);
        if (lane == 0) {
            g_pos[r0 + i] = 2.0f * d;
            g_denom[r0 + i] = 0.0f;
        }
    }
}

__device__ __forceinline__ void ldsm_x4(uint32_t (&r)[4], uint32_t addr) {
    asm volatile("ldmatrix.sync.aligned.m8n8.x4.shared.b16 {%0,%1,%2,%3}, [%4];"
                 : "=r"(r[0]), "=r"(r[1]), "=r"(r[2]), "=r"(r[3]) : "r"(addr));
}

// fp16 in, fp16 accum: C/D fragments are 2 regs of f16x2
__device__ __forceinline__ void hmma_f16acc(uint32_t (&c)[2], const uint32_t (&a)[4],
                                            uint32_t b0, uint32_t b1) {
    asm volatile(
        "mma.sync.aligned.m16n8k16.row.col.f16.f16.f16.f16 "
        "{%0,%1}, {%2,%3,%4,%5}, {%6,%7}, {%0,%1};"
        : "+r"(c[0]), "+r"(c[1])
        : "r"(a[0]), "r"(a[1]), "r"(a[2]), "r"(a[3]), "r"(b0), "r"(b1));
}

__device__ __forceinline__ void cp16(uint32_t dst, const void* src) {
    asm volatile("cp.async.cg.shared.global [%0], [%1], 16;"
                 :: "r"(dst), "l"(src) : "memory");
}

// One tile's k-loop accumulating into `acc`, with the epilogue of the
// PREVIOUS tile (`cprev`) interleaved one fragment-group per kk step.
// All register-array indices are compile-time (no spills).
__device__ __forceinline__ void tile_step(
    uint32_t (&acc)[2][4][2], uint32_t (&cprev)[2][4][2],
    uint32_t a_base, uint32_t b_base, float (&rs)[4]) {
    #pragma unroll
    for (int kk = 0; kk < 8; ++kk) {
        const uint32_t koff = (uint32_t)kk * 32;
        uint32_t a[2][4];
        #pragma unroll
        for (int mf = 0; mf < 2; ++mf)
            ldsm_x4(a[mf], a_base + (uint32_t)(mf * 16) * SROW + koff);
        uint32_t bm[2][4];
        #pragma unroll
        for (int nf2 = 0; nf2 < 2; ++nf2)
            ldsm_x4(bm[nf2], b_base + (uint32_t)(nf2 * 16) * SROW + koff);

        #pragma unroll
        for (int mf = 0; mf < 2; ++mf)
            #pragma unroll
            for (int nf = 0; nf < 4; ++nf)
                hmma_f16acc(acc[mf][nf], a[mf],
                            bm[nf >> 1][nf & 1], bm[nf >> 1][(nf & 1) + 2]);

        {   // deferred epilogue chunk: fragment group = kk of previous tile
            const int mf = kk >> 2, nf = kk & 3;
            float2 f0 = __half22float2(*(__half2*)&cprev[mf][nf][0]);
            float2 f1 = __half22float2(*(__half2*)&cprev[mf][nf][1]);
            float e0, e1, e2, e3;
            asm("ex2.approx.f32 %0, %1;" : "=f"(e0) : "f"(f0.x));
            asm("ex2.approx.f32 %0, %1;" : "=f"(e1) : "f"(f0.y));
            asm("ex2.approx.f32 %0, %1;" : "=f"(e2) : "f"(f1.x));
            asm("ex2.approx.f32 %0, %1;" : "=f"(e3) : "f"(f1.y));
            rs[mf * 2 + 0] += e0 + e1;
            rs[mf * 2 + 1] += e2 + e3;
            cprev[mf][nf][0] = 0u;
            cprev[mf][nf][1] = 0u;
        }
    }
}

// ---------------------------------------------------------------------------
// FP16-accum HMMA GEMM + fused deferred exp/rowsum (R9 structure, verified).
// Grid (N/128 row-tiles, JCHUNKS j-chunks), 512 threads (16 warps 4x4).
// Warp tile 32x32. A persistent; B double-buffered; loop unrolled x2 with
// static accumulator sets c0/c1. Tile 0's bogus epilogue of zeros adds
// exactly 128*JCHUNKS per row; subtracted in loss_kernel.
// ---------------------------------------------------------------------------
__global__ void __launch_bounds__(THREADS, 1)
gemm_hmma16_kernel(int N) {
    extern __shared__ char smem[];
    const uint32_t sb = smem_u32(smem);
    const int tid = threadIdx.x;
    const int wid = tid >> 5;
    const int lane = tid & 31;
    const int warp_m = wid >> 2;      // 0..3
    const int warp_n = wid & 3;       // 0..3
    const int i0 = blockIdx.x * BM;
    const int T = (N / BNT) / JCHUNKS;   // 16 tiles per chunk (even)
    const int jt0 = blockIdx.y * T;

    // Load A tile (128x128 fp16) into padded smem.
    {
        const uint4* A4 = (const uint4*)(g_z1h + (size_t)i0 * D);
        #pragma unroll
        for (int t = 0; t < 4; ++t) {
            int idx = tid + t * THREADS;        // 0..2047
            int r = idx >> 4, c = idx & 15;
            *(uint4*)(smem + OFF_A + r * SROW + c * 16) = A4[idx];
        }
    }

    // Prologue: B tile jt0 -> buf0
    {
        const char* B = (const char*)(g_z2h + (size_t)jt0 * BNT * D);
        #pragma unroll
        for (int t = 0; t < 4; ++t) {
            int idx = tid + t * THREADS;
            int r = idx >> 4, c = idx & 15;
            cp16(sb + OFF_B0 + r * SROW + c * 16, B + (size_t)r * 256 + c * 16);
        }
        asm volatile("cp.async.commit_group;" ::: "memory");
    }

    const uint32_t a_base = sb + OFF_A +
        (uint32_t)(warp_m * 32 + (lane & 15)) * SROW + (uint32_t)((lane >> 4) * 16);
    const uint32_t b_lane_off =
        (uint32_t)(warp_n * 32 + (lane & 15)) * SROW + (uint32_t)((lane >> 4) * 16);
    const uint32_t b_base0 = sb + OFF_B0 + b_lane_off;
    const uint32_t b_base1 = sb + OFF_B1 + b_lane_off;

    uint32_t c0[2][4][2], c1[2][4][2];
    #pragma unroll
    for (int mf = 0; mf < 2; ++mf)
        #pragma unroll
        for (int nf = 0; nf < 4; ++nf) {
            c0[mf][nf][0] = 0u; c0[mf][nf][1] = 0u;
            c1[mf][nf][0] = 0u; c1[mf][nf][1] = 0u;
        }

    float rs[4] = {0.f, 0.f, 0.f, 0.f};

    for (int t = 0; t < T; t += 2) {
        // ---- sub-iter A: tile t (buf0, acc c0, epilogue c1 = tile t-1) ----
        __syncthreads();   // everyone done reading buf1
        {   // t+1 < T always (T even, t <= T-2)
            const char* B = (const char*)(g_z2h + (size_t)(jt0 + t + 1) * BNT * D);
            #pragma unroll
            for (int u = 0; u < 4; ++u) {
                int idx = tid + u * THREADS;
                int r = idx >> 4, ch = idx & 15;
                cp16(sb + OFF_B1 + r * SROW + ch * 16, B + (size_t)r * 256 + ch * 16);
            }
            asm volatile("cp.async.commit_group;" ::: "memory");
            asm volatile("cp.async.wait_group 1;" ::: "memory");
        }
        __syncthreads();   // buf0 visible
        tile_step(c0, c1, a_base, b_base0, rs);

        // ---- sub-iter B: tile t+1 (buf1, acc c1, epilogue c0 = tile t) ----
        __syncthreads();   // everyone done reading buf0
        if (t + 2 < T) {
            const char* B = (const char*)(g_z2h + (size_t)(jt0 + t + 2) * BNT * D);
            #pragma unroll
            for (int u = 0; u < 4; ++u) {
                int idx = tid + u * THREADS;
                int r = idx >> 4, ch = idx & 15;
                cp16(sb + OFF_B0 + r * SROW + ch * 16, B + (size_t)r * 256 + ch * 16);
            }
            asm volatile("cp.async.commit_group;" ::: "memory");
            asm volatile("cp.async.wait_group 1;" ::: "memory");
        } else {
            asm volatile("cp.async.wait_group 0;" ::: "memory");
        }
        __syncthreads();   // buf1 visible
        tile_step(c1, c0, a_base, b_base1, rs);
    }

    // final epilogue: c1 holds tile T-1
    #pragma unroll
    for (int mf = 0; mf < 2; ++mf) {
        float lo = 0.f, hi = 0.f;
        #pragma unroll
        for (int nf = 0; nf < 4; ++nf) {
            float2 f0 = __half22float2(*(__half2*)&c1[mf][nf][0]);
            float2 f1 = __half22float2(*(__half2*)&c1[mf][nf][1]);
            float e0, e1, e2, e3;
            asm("ex2.approx.f32 %0, %1;" : "=f"(e0) : "f"(f0.x));
            asm("ex2.approx.f32 %0, %1;" : "=f"(e1) : "f"(f0.y));
            asm("ex2.approx.f32 %0, %1;" : "=f"(e2) : "f"(f1.x));
            asm("ex2.approx.f32 %0, %1;" : "=f"(e3) : "f"(f1.y));
            lo += e0 + e1;
            hi += e2 + e3;
        }
        rs[mf * 2 + 0] += lo;
        rs[mf * 2 + 1] += hi;
    }

    // reduce rs across the 4 lanes of each quad (same row group)
    #pragma unroll
    for (int i = 0; i < 4; ++i) {
        rs[i] += __shfl_xor_sync(0xFFFFFFFFu, rs[i], 1);
        rs[i] += __shfl_xor_sync(0xFFFFFFFFu, rs[i], 2);
    }

    float* red = (float*)(smem + OFF_RED);
    __syncthreads();
    if (tid < 128) red[tid] = 0.f;
    __syncthreads();
    if ((lane & 3) == 0) {
        #pragma unroll
        for (int mf = 0; mf < 2; ++mf) {
            #pragma unroll
            for (int sub = 0; sub < 2; ++sub) {
                int row = warp_m * 32 + mf * 16 + sub * 8 + (lane >> 2);
                atomicAdd(&red[row], rs[mf * 2 + sub]);
            }
        }
    }
    __syncthreads();
    if (tid < 128) atomicAdd(&g_denom[i0 + tid], red[tid]);
}

// 64 blocks x 256 threads; per-block partial, atomicAdd into out[0].
// log(x) = lg2.approx(x) * ln2 (MUFU instead of slow logf).
__global__ void loss_kernel(float* __restrict__ out, int N) {
    __shared__ float smr[256];
    const float BOGUS = 128.0f * (float)JCHUNKS;   // bogus first-epilogue
    const float LN2 = 0.6931471805599453f;
    int i = blockIdx.x * 256 + threadIdx.x;        // N = 64*256 exactly
    float dv = g_denom[i] - BOGUS + 1e-8f;
    float lg;
    asm("lg2.approx.f32 %0, %1;" : "=f"(lg) : "f"(dv));
    float s = lg * LN2 - g_pos[i];
    smr[threadIdx.x] = s;
    __syncthreads();
    #pragma unroll
    for (int off = 128; off > 0; off >>= 1) {
        if (threadIdx.x < off) smr[threadIdx.x] += smr[threadIdx.x + off];
        __syncthreads();
    }
    if (threadIdx.x == 0) atomicAdd(out, smr[0] / (float)N);
}

extern "C" void kernel_launch(void* const* d_in, const int* in_sizes, int n_in,
                              void* d_out, int out_size) {
    const float* z1 = (const float*)d_in[0];
    const float* z2 = (const float*)d_in[1];
    float* out = (float*)d_out;
    const int N = in_sizes[0] / D;  // 16384

    cudaFuncSetAttribute(gemm_hmma16_kernel,
                         cudaFuncAttributeMaxDynamicSharedMemorySize,
                         (int)SMEM_BYTES);

    norm_kernel<<<N / 32, 256>>>(z1, z2, out, N);  // 4 rows/warp, 8 warps/block
    dim3 grid(N / BM, JCHUNKS);
    gemm_hmma16_kernel<<<grid, THREADS, SMEM_BYTES>>>(N);
    loss_kernel<<<N / 256, 256>>>(out, N);
}

// round 14
// speedup vs baseline: 1.4588x; 1.0068x over previous
#include <cuda_runtime.h>
#include <cuda_fp16.h>
#include <math.h>
#include <stdint.h>

#define D 128
#define N_MAX 16384
#define BM 128
#define BNT 128
#define THREADS 512
#define JCHUNKS 8
#define NITEMS 1024          // (N/BM) * JCHUNKS
#define GRID_P 148           // persistent CTAs, 1 per SM

// Scratch (allocation-free rule: __device__ globals)
__device__ __half g_z1h[N_MAX * D];   // fp16, pre-scaled by 2/ln2
__device__ __half g_z2h[N_MAX * D];   // fp16
__device__ float g_denom[N_MAX];
__device__ float g_pos[N_MAX];
__device__ int g_ctr;                 // persistent work counter

// padded smem row stride: 128 fp16 + 8 pad = 136 elems = 272 bytes
#define SROW 272
#define TILE_BYTES (128 * SROW)          // 34816
#define OFF_A 0
#define OFF_B0 TILE_BYTES
#define OFF_B1 (2 * TILE_BYTES)
#define OFF_RED (3 * TILE_BYTES)
#define OFF_ITEM (OFF_RED + 128 * 4)
#define SMEM_BYTES (OFF_ITEM + 16)

__device__ __forceinline__ uint32_t smem_u32(const void* p) {
    uint32_t a;
    asm("{ .reg .u64 t; cvta.to.shared.u64 t, %1; cvt.u32.u64 %0, t; }"
        : "=r"(a) : "l"(p));
    return a;
}

__device__ __forceinline__ float warp_sum(float v) {
    #pragma unroll
    for (int off = 16; off > 0; off >>= 1)
        v += __shfl_xor_sync(0xFFFFFFFFu, v, off);
    return v;
}

// One warp per row: fp32 normalize, exact fp32 pos, fp16 copies;
// zeroes g_denom, g_ctr, out[0].
__global__ void norm_kernel(const float* __restrict__ z1,
                            const float* __restrict__ z2,
                            float* __restrict__ out, int N) {
    int warp = (blockIdx.x * blockDim.x + threadIdx.x) >> 5;
    int lane = threadIdx.x & 31;
    if (blockIdx.x == 0 && threadIdx.x == 0) { out[0] = 0.0f; g_ctr = 0; }
    if (warp >= N) return;

    const float4 a = ((const float4*)(z1 + (size_t)warp * D))[lane];
    const float4 b = ((const float4*)(z2 + (size_t)warp * D))[lane];

    float sa = a.x * a.x + a.y * a.y + a.z * a.z + a.w * a.w;
    float sb = b.x * b.x + b.y * b.y + b.z * b.z + b.w * b.w;
    sa = warp_sum(sa);
    sb = warp_sum(sb);

    float inva = 1.0f / fmaxf(sqrtf(sa), 1e-12f);
    float invb = 1.0f / fmaxf(sqrtf(sb), 1e-12f);

    float4 an = make_float4(a.x * inva, a.y * inva, a.z * inva, a.w * inva);
    float4 bn = make_float4(b.x * invb, b.y * invb, b.z * invb, b.w * invb);

    // bake exponent scale 2/ln2 into A so epilogue is a bare ex2.approx
    const float S = 2.8853900817779268f;
    __half2 a01 = __floats2half2_rn(an.x * S, an.y * S);
    __half2 a23 = __floats2half2_rn(an.z * S, an.w * S);
    __half2 b01 = __floats2half2_rn(bn.x, bn.y);
    __half2 b23 = __floats2half2_rn(bn.z, bn.w);

    uint2 pa, pb;
    pa.x = *(uint32_t*)&a01; pa.y = *(uint32_t*)&a23;
    pb.x = *(uint32_t*)&b01; pb.y = *(uint32_t*)&b23;
    ((uint2*)(g_z1h + (size_t)warp * D))[lane] = pa;
    ((uint2*)(g_z2h + (size_t)warp * D))[lane] = pb;

    float d = an.x * bn.x + an.y * bn.y + an.z * bn.z + an.w * bn.w;
    d = warp_sum(d);
    if (lane == 0) {
        g_pos[warp] = 2.0f * d;
        g_denom[warp] = 0.0f;
    }
}

__device__ __forceinline__ void ldsm_x4(uint32_t (&r)[4], uint32_t addr) {
    asm volatile("ldmatrix.sync.aligned.m8n8.x4.shared.b16 {%0,%1,%2,%3}, [%4];"
                 : "=r"(r[0]), "=r"(r[1]), "=r"(r[2]), "=r"(r[3]) : "r"(addr));
}

// fp16 in, fp16 accum: C/D fragments are 2 regs of f16x2
__device__ __forceinline__ void hmma_f16acc(uint32_t (&c)[2], const uint32_t (&a)[4],
                                            uint32_t b0, uint32_t b1) {
    asm volatile(
        "mma.sync.aligned.m16n8k16.row.col.f16.f16.f16.f16 "
        "{%0,%1}, {%2,%3,%4,%5}, {%6,%7}, {%0,%1};"
        : "+r"(c[0]), "+r"(c[1])
        : "r"(a[0]), "r"(a[1]), "r"(a[2]), "r"(a[3]), "r"(b0), "r"(b1));
}

__device__ __forceinline__ void cp16(uint32_t dst, const void* src) {
    asm volatile("cp.async.cg.shared.global [%0], [%1], 16;"
                 :: "r"(dst), "l"(src) : "memory");
}

// One tile's k-loop accumulating into `acc`, with the epilogue of the
// PREVIOUS tile (`cprev`) interleaved one fragment-group per kk step.
// All register-array indices are compile-time (no spills).
__device__ __forceinline__ void tile_step(
    uint32_t (&acc)[2][4][2], uint32_t (&cprev)[2][4][2],
    uint32_t a_base, uint32_t b_base, float (&rs)[4]) {
    #pragma unroll
    for (int kk = 0; kk < 8; ++kk) {
        const uint32_t koff = (uint32_t)kk * 32;
        uint32_t a[2][4];
        #pragma unroll
        for (int mf = 0; mf < 2; ++mf)
            ldsm_x4(a[mf], a_base + (uint32_t)(mf * 16) * SROW + koff);
        uint32_t bm[2][4];
        #pragma unroll
        for (int nf2 = 0; nf2 < 2; ++nf2)
            ldsm_x4(bm[nf2], b_base + (uint32_t)(nf2 * 16) * SROW + koff);

        #pragma unroll
        for (int mf = 0; mf < 2; ++mf)
            #pragma unroll
            for (int nf = 0; nf < 4; ++nf)
                hmma_f16acc(acc[mf][nf], a[mf],
                            bm[nf >> 1][nf & 1], bm[nf >> 1][(nf & 1) + 2]);

        {   // deferred epilogue chunk: fragment group = kk of previous tile
            const int mf = kk >> 2, nf = kk & 3;
            float2 f0 = __half22float2(*(__half2*)&cprev[mf][nf][0]);
            float2 f1 = __half22float2(*(__half2*)&cprev[mf][nf][1]);
            float e0, e1, e2, e3;
            asm("ex2.approx.f32 %0, %1;" : "=f"(e0) : "f"(f0.x));
            asm("ex2.approx.f32 %0, %1;" : "=f"(e1) : "f"(f0.y));
            asm("ex2.approx.f32 %0, %1;" : "=f"(e2) : "f"(f1.x));
            asm("ex2.approx.f32 %0, %1;" : "=f"(e3) : "f"(f1.y));
            rs[mf * 2 + 0] += e0 + e1;
            rs[mf * 2 + 1] += e2 + e3;
            cprev[mf][nf][0] = 0u;
            cprev[mf][nf][1] = 0u;
        }
    }
}

// ---------------------------------------------------------------------------
// PERSISTENT FP16-accum HMMA GEMM + fused deferred exp/rowsum.
// Grid 148 CTAs (1/SM), 512 threads. Atomic counter pops work items
// (row-tile, chunk); per item the verified R9 16-tile loop runs unchanged.
// Bogus first-epilogue per item adds 128/row; 8 items cover each row ->
// 1024/row, subtracted in loss_kernel.
// ---------------------------------------------------------------------------
__global__ void __launch_bounds__(THREADS, 1)
gemm_hmma16_kernel(int N) {
    extern __shared__ char smem[];
    const uint32_t sb = smem_u32(smem);
    const int tid = threadIdx.x;
    const int wid = tid >> 5;
    const int lane = tid & 31;
    const int warp_m = wid >> 2;      // 0..3
    const int warp_n = wid & 3;       // 0..3
    const int T = (N / BNT) / JCHUNKS;   // 16 tiles per item (even)
    float* red = (float*)(smem + OFF_RED);
    int* item_sm = (int*)(smem + OFF_ITEM);

    const uint32_t a_lane_off =
        (uint32_t)(warp_m * 32 + (lane & 15)) * SROW + (uint32_t)((lane >> 4) * 16);
    const uint32_t b_lane_off =
        (uint32_t)(warp_n * 32 + (lane & 15)) * SROW + (uint32_t)((lane >> 4) * 16);
    const uint32_t a_base = sb + OFF_A + a_lane_off;
    const uint32_t b_base0 = sb + OFF_B0 + b_lane_off;
    const uint32_t b_base1 = sb + OFF_B1 + b_lane_off;

    uint32_t c0[2][4][2], c1[2][4][2];
    #pragma unroll
    for (int mf = 0; mf < 2; ++mf)
        #pragma unroll
        for (int nf = 0; nf < 4; ++nf) {
            c0[mf][nf][0] = 0u; c0[mf][nf][1] = 0u;
            c1[mf][nf][0] = 0u; c1[mf][nf][1] = 0u;
        }

    for (;;) {
        // ---- pop next work item ----
        if (tid == 0) item_sm[0] = atomicAdd(&g_ctr, 1);
        __syncthreads();                 // item visible; prev item fully done
        const int item = item_sm[0];
        if (item >= NITEMS) break;
        const int i0 = (item >> 3) * BM;       // row tile
        const int jt0 = (item & 7) * T;        // chunk start tile

        // Load A tile (128x128 fp16) into padded smem.
        {
            const uint4* A4 = (const uint4*)(g_z1h + (size_t)i0 * D);
            #pragma unroll
            for (int t = 0; t < 4; ++t) {
                int idx = tid + t * THREADS;        // 0..2047
                int r = idx >> 4, c = idx & 15;
                *(uint4*)(smem + OFF_A + r * SROW + c * 16) = A4[idx];
            }
        }
        // Prologue: B tile jt0 -> buf0
        {
            const char* B = (const char*)(g_z2h + (size_t)jt0 * BNT * D);
            #pragma unroll
            for (int t = 0; t < 4; ++t) {
                int idx = tid + t * THREADS;
                int r = idx >> 4, c = idx & 15;
                cp16(sb + OFF_B0 + r * SROW + c * 16, B + (size_t)r * 256 + c * 16);
            }
            asm volatile("cp.async.commit_group;" ::: "memory");
        }
        if (tid < 128) red[tid] = 0.f;

        float rs[4] = {0.f, 0.f, 0.f, 0.f};

        for (int t = 0; t < T; t += 2) {
            // sub-iter A: tile t (buf0, acc c0, epilogue c1 = tile t-1)
            __syncthreads();   // everyone done reading buf1 (or: A/buf0 ready)
            {   // t+1 < T always (T even)
                const char* B = (const char*)(g_z2h + (size_t)(jt0 + t + 1) * BNT * D);
                #pragma unroll
                for (int u = 0; u < 4; ++u) {
                    int idx = tid + u * THREADS;
                    int r = idx >> 4, ch = idx & 15;
                    cp16(sb + OFF_B1 + r * SROW + ch * 16, B + (size_t)r * 256 + ch * 16);
                }
                asm volatile("cp.async.commit_group;" ::: "memory");
                asm volatile("cp.async.wait_group 1;" ::: "memory");
            }
            __syncthreads();   // buf0 visible
            tile_step(c0, c1, a_base, b_base0, rs);

            // sub-iter B: tile t+1 (buf1, acc c1, epilogue c0 = tile t)
            __syncthreads();   // everyone done reading buf0
            if (t + 2 < T) {
                const char* B = (const char*)(g_z2h + (size_t)(jt0 + t + 2) * BNT * D);
                #pragma unroll
                for (int u = 0; u < 4; ++u) {
                    int idx = tid + u * THREADS;
                    int r = idx >> 4, ch = idx & 15;
                    cp16(sb + OFF_B0 + r * SROW + ch * 16, B + (size_t)r * 256 + ch * 16);
                }
                asm volatile("cp.async.commit_group;" ::: "memory");
                asm volatile("cp.async.wait_group 1;" ::: "memory");
            } else {
                asm volatile("cp.async.wait_group 0;" ::: "memory");
            }
            __syncthreads();   // buf1 visible
            tile_step(c1, c0, a_base, b_base1, rs);
        }

        // final epilogue: c1 holds tile T-1 (zero it for reuse next item)
        #pragma unroll
        for (int mf = 0; mf < 2; ++mf) {
            float lo = 0.f, hi = 0.f;
            #pragma unroll
            for (int nf = 0; nf < 4; ++nf) {
                float2 f0 = __half22float2(*(__half2*)&c1[mf][nf][0]);
                float2 f1 = __half22float2(*(__half2*)&c1[mf][nf][1]);
                float e0, e1, e2, e3;
                asm("ex2.approx.f32 %0, %1;" : "=f"(e0) : "f"(f0.x));
                asm("ex2.approx.f32 %0, %1;" : "=f"(e1) : "f"(f0.y));
                asm("ex2.approx.f32 %0, %1;" : "=f"(e2) : "f"(f1.x));
                asm("ex2.approx.f32 %0, %1;" : "=f"(e3) : "f"(f1.y));
                lo += e0 + e1;
                hi += e2 + e3;
                c1[mf][nf][0] = 0u;
                c1[mf][nf][1] = 0u;
            }
            rs[mf * 2 + 0] += lo;
            rs[mf * 2 + 1] += hi;
        }

        // reduce rs across the 4 lanes of each quad
        #pragma unroll
        for (int i = 0; i < 4; ++i) {
            rs[i] += __shfl_xor_sync(0xFFFFFFFFu, rs[i], 1);
            rs[i] += __shfl_xor_sync(0xFFFFFFFFu, rs[i], 2);
        }
        __syncthreads();   // red zeroed (above) and all compute done
        if ((lane & 3) == 0) {
            #pragma unroll
            for (int mf = 0; mf < 2; ++mf)
                #pragma unroll
                for (int sub = 0; sub < 2; ++sub) {
                    int row = warp_m * 32 + mf * 16 + sub * 8 + (lane >> 2);
                    atomicAdd(&red[row], rs[mf * 2 + sub]);
                }
        }
        __syncthreads();
        if (tid < 128) atomicAdd(&g_denom[i0 + tid], red[tid]);
        // loop back: first __syncthreads of next item protects A/red reuse
    }
}

// 64 blocks x 256 threads; per-block partial, atomicAdd into out[0].
// log(x) = lg2.approx(x) * ln2 (MUFU instead of slow logf).
__global__ void loss_kernel(float* __restrict__ out, int N) {
    __shared__ float smr[256];
    const float BOGUS = 128.0f * (float)JCHUNKS;   // bogus first-epilogue
    const float LN2 = 0.6931471805599453f;
    int i = blockIdx.x * 256 + threadIdx.x;        // N = 64*256 exactly
    float dv = g_denom[i] - BOGUS + 1e-8f;
    float lg;
    asm("lg2.approx.f32 %0, %1;" : "=f"(lg) : "f"(dv));
    float s = lg * LN2 - g_pos[i];
    smr[threadIdx.x] = s;
    __syncthreads();
    #pragma unroll
    for (int off = 128; off > 0; off >>= 1) {
        if (threadIdx.x < off) smr[threadIdx.x] += smr[threadIdx.x + off];
        __syncthreads();
    }
    if (threadIdx.x == 0) atomicAdd(out, smr[0] / (float)N);
}

extern "C" void kernel_launch(void* const* d_in, const int* in_sizes, int n_in,
                              void* d_out, int out_size) {
    const float* z1 = (const float*)d_in[0];
    const float* z2 = (const float*)d_in[1];
    float* out = (float*)d_out;
    const int N = in_sizes[0] / D;  // 16384

    cudaFuncSetAttribute(gemm_hmma16_kernel,
                         cudaFuncAttributeMaxDynamicSharedMemorySize,
                         (int)SMEM_BYTES);

    norm_kernel<<<(N + 7) / 8, 256>>>(z1, z2, out, N);
    gemm_hmma16_kernel<<<GRID_P, THREADS, SMEM_BYTES>>>(N);
    loss_kernel<<<N / 256, 256>>>(out, N);
}